// round 9
// baseline (speedup 1.0000x reference)
#include <cuda_runtime.h>
#include <cstdint>

#define NL 8
#define T_STATIC 524288u   // 2^19
#define T_XY     32768u    // 2^15
#define T_PL     8192u     // 2^13
#define P1 2654435761u
#define P2 805459861u

#define NXY (NL * T_XY)    // 262144
#define NPL (NL * T_PL)    // 65536

__device__ float g_scales[NL];
__device__ float g_red_xy[NXY];
__device__ float g_red_xz[NPL];
__device__ float g_red_yz[NPL];

// ---------------------------------------------------------------------------
// Init scales (double, matches numpy) + fold time-blend and Lagrange basis
// into scalar tables for all three planes.
// ---------------------------------------------------------------------------
__global__ void reduce_all_kernel(const float4* __restrict__ txy,
                                  const float4* __restrict__ txz,
                                  const float4* __restrict__ tyz,
                                  const float* __restrict__ tptr) {
    int g = blockIdx.x * blockDim.x + threadIdx.x;
    if (g < NL) {
        double s = exp2((double)g * (6.0 / 7.0)) * 512.0 - 1.0;
        g_scales[g] = (float)s;
    }

    float t = __ldg(tptr);
    float idxf = t * 7.0f;               // t * (TIME_RES - 1)
    float fi1 = floorf(idxf);
    int i1 = (int)fi1;
    int i2 = (int)ceilf(idxf);
    float w2 = idxf - fi1;
    float w1 = 1.0f - w2;

    float tn[4] = {0.0f, 1.0f / 3.0f, 2.0f / 3.0f, 1.0f};
    float coef[4];
#pragma unroll
    for (int ii = 0; ii < 4; ii++) {
        float c = 1.0f;
#pragma unroll
        for (int m = 0; m < 4; m++)
            if (m != ii) c = c * (t - tn[m]) / (tn[ii] - tn[m]);
        coef[ii] = c;
    }

    const float4* tab;
    float* dst;
    int e, total;
    if (g < (int)NXY)                  { tab = txy; dst = g_red_xy; e = g;             total = NXY; }
    else if (g < (int)(NXY + NPL))     { tab = txz; dst = g_red_xz; e = g - NXY;       total = NPL; }
    else if (g < (int)(NXY + 2 * NPL)) { tab = tyz; dst = g_red_yz; e = g - NXY - NPL; total = NPL; }
    else return;

    float4 v1 = __ldg(tab + (size_t)i1 * total + e);
    float4 v2 = __ldg(tab + (size_t)i2 * total + e);
    dst[e] = coef[0] * (w1 * v1.x + w2 * v2.x)
           + coef[1] * (w1 * v1.y + w2 * v2.y)
           + coef[2] * (w1 * v1.z + w2 * v2.z)
           + coef[3] * (w1 * v1.w + w2 * v2.w);
}

// ---------------------------------------------------------------------------
// Static 3D hash-grid, corner-per-lane layout: warp = 4 points x 8 corners,
// looping over 8 levels. x-paired corners (lanes 2k/2k+1) hit the SAME 128B
// line whenever ux is even (hash prime for x is 1 => indices e, e^1), so L1
// merges them into one wavefront: expected 6 lines per point-level vs 8.
// Cross-lane sum via 3 butterfly shuffles; lane c keeps level c's float4 so
// final stores are 512B contiguous per warp.
// ---------------------------------------------------------------------------
__global__ void __launch_bounds__(256)
static_kernel(const float* __restrict__ x,
              const float4* __restrict__ tstat,
              float4* __restrict__ out_s,   // [N*8] float4, level-major per point
              int N) {
    int warp_g = (blockIdx.x * 256 + threadIdx.x) >> 5;
    int lane = threadIdx.x & 31;
    int pg = warp_g * 4 + (lane >> 3);        // point id this lane serves
    unsigned c = (unsigned)lane & 7u;         // corner id
    int p = (pg < N) ? pg : (N - 1);          // clamp for safe loads

    float x0 = __ldg(x + 3 * (size_t)p + 0);
    float x1 = __ldg(x + 3 * (size_t)p + 1);
    float x2 = __ldg(x + 3 * (size_t)p + 2);

    uint32_t cx = c & 1u, cy = (c >> 1) & 1u, cz = (c >> 2) & 1u;

    float o0 = 0.f, o1 = 0.f, o2 = 0.f, o3 = 0.f;

#pragma unroll
    for (int l = 0; l < NL; l++) {
        float scl = g_scales[l];
        float px = __fadd_rn(__fmul_rn(x0, scl), 0.5f);
        float py = __fadd_rn(__fmul_rn(x1, scl), 0.5f);
        float pz = __fadd_rn(__fmul_rn(x2, scl), 0.5f);
        float bx = floorf(px), by = floorf(py), bz = floorf(pz);
        float fx = px - bx, fy = py - by, fz = pz - bz;
        uint32_t ux = (uint32_t)bx, uy = (uint32_t)by, uz = (uint32_t)bz;

        uint32_t h = (ux + cx) ^ (uy * P1 + (cy ? P1 : 0u))
                               ^ (uz * P2 + (cz ? P2 : 0u));
        float w = (cx ? fx : 1.0f - fx) * (cy ? fy : 1.0f - fy)
                * (cz ? fz : 1.0f - fz);

        float4 v = __ldg(tstat + (size_t)l * T_STATIC + (h & (T_STATIC - 1u)));

        float b0 = w * v.x, b1 = w * v.y, b2 = w * v.z, b3 = w * v.w;
#pragma unroll
        for (int off = 1; off < 8; off <<= 1) {
            b0 += __shfl_xor_sync(0xffffffffu, b0, off);
            b1 += __shfl_xor_sync(0xffffffffu, b1, off);
            b2 += __shfl_xor_sync(0xffffffffu, b2, off);
            b3 += __shfl_xor_sync(0xffffffffu, b3, off);
        }
        if (c == (unsigned)l) { o0 = b0; o1 = b1; o2 = b2; o3 = b3; }
    }

    if (pg < N)
        out_s[(size_t)pg * 8 + c] = make_float4(o0, o1, o2, o3);
}

// ---------------------------------------------------------------------------
// Dynamic planes: one thread per (point, plane). 8 levels x ~3 loads each
// (even-ua corners pair into one float2). Coalesced 32B stores per thread.
// ---------------------------------------------------------------------------
__global__ void __launch_bounds__(256)
dyn_kernel(const float* __restrict__ x,
           float4* __restrict__ out_d,   // [N*6] float4
           int total /* N*3 */) {
    int g = blockIdx.x * blockDim.x + threadIdx.x;
    if (g >= total) return;
    unsigned p = (unsigned)g / 3u;
    unsigned plane = (unsigned)g - 3u * p;

    float x0 = __ldg(x + 3 * (size_t)p + 0);
    float x1 = __ldg(x + 3 * (size_t)p + 1);
    float x2 = __ldg(x + 3 * (size_t)p + 2);

    float a = (plane == 2u) ? x1 : x0;
    float b = (plane == 0u) ? x1 : x2;
    const float* red = (plane == 0u) ? g_red_xy
                     : (plane == 1u) ? g_red_xz : g_red_yz;
    uint32_t mask = (plane == 0u) ? (T_XY - 1u) : (T_PL - 1u);
    uint32_t tsize = mask + 1u;

    float d8[NL];
#pragma unroll
    for (int l = 0; l < NL; l++) {
        float s = g_scales[l];
        float pa = __fadd_rn(__fmul_rn(a, s), 0.5f);
        float pb = __fadd_rn(__fmul_rn(b, s), 0.5f);
        float ba = floorf(pa), bb = floorf(pb);
        float fa = pa - ba, fb = pb - bb;
        uint32_t ua = (uint32_t)ba, ub = (uint32_t)bb;
        uint32_t hb0 = ub * P1, hb1 = hb0 + P1;
        uint32_t e00 = (ua ^ hb0) & mask;
        uint32_t e01 = (ua ^ hb1) & mask;
        const float* r = red + (size_t)l * tsize;

        float v00, v10, v01, v11;
        if ((ua & 1u) == 0u) {
            // e10 == e00^1, e11 == e01^1 (no carry out of bit 0)
            float2 q0 = __ldg((const float2*)(r + (e00 & ~1u)));
            float2 q1 = __ldg((const float2*)(r + (e01 & ~1u)));
            if (e00 & 1u) { v00 = q0.y; v10 = q0.x; } else { v00 = q0.x; v10 = q0.y; }
            if (e01 & 1u) { v01 = q1.y; v11 = q1.x; } else { v01 = q1.x; v11 = q1.y; }
        } else {
            uint32_t e10 = ((ua + 1u) ^ hb0) & mask;
            uint32_t e11 = ((ua + 1u) ^ hb1) & mask;
            v00 = __ldg(r + e00); v10 = __ldg(r + e10);
            v01 = __ldg(r + e01); v11 = __ldg(r + e11);
        }

        float ga = 1.0f - fa, gb = 1.0f - fb;
        float acc = (ga * gb) * v00;
        acc += (fa * gb) * v10;
        acc += (ga * fb) * v01;
        acc += (fa * fb) * v11;
        d8[l] = acc;
    }

    float4* od = out_d + (size_t)g * 2;
    od[0] = make_float4(d8[0], d8[1], d8[2], d8[3]);
    od[1] = make_float4(d8[4], d8[5], d8[6], d8[7]);
}

// ---------------------------------------------------------------------------
extern "C" void kernel_launch(void* const* d_in, const int* in_sizes, int n_in,
                              void* d_out, int out_size) {
    const float* x     = (const float*)d_in[0];
    const float* tptr  = (const float*)d_in[1];
    const float* tstat = (const float*)d_in[2];
    const float* txy   = (const float*)d_in[3];
    const float* txz   = (const float*)d_in[4];
    const float* tyz   = (const float*)d_in[5];

    int N = in_sizes[0] / 3;
    float* out_s = (float*)d_out;
    float* out_d = (float*)d_out + (size_t)N * 32;

    int total_red = NXY + 2 * NPL;
    reduce_all_kernel<<<(total_red + 255) / 256, 256>>>(
        (const float4*)txy, (const float4*)txz, (const float4*)tyz, tptr);

    int tot_d = N * 3;
    dyn_kernel<<<(tot_d + 255) / 256, 256>>>(x, (float4*)out_d, tot_d);

    // static last so ncu's -s 5 lands on it (it has no dependency on reduce)
    int nwarps = (N + 3) / 4;
    int nblocks = (nwarps + 7) / 8;           // 8 warps per 256-thread block
    static_kernel<<<nblocks, 256>>>(x, (const float4*)tstat, (float4*)out_s, N);
}